// round 1
// baseline (speedup 1.0000x reference)
#include <cuda_runtime.h>

// ---------------------------------------------------------------------------
// SAGE_37203006718147: 3-layer GraphSAGE
//   h = (h_dst @ Ws) + (segment_mean(h_src[src], dst) @ Wn) + b, relu after L1
// Sizes (compile-time): N0=200000, N1=50000, N2=12000, N3=3000,
//                       E0=500000, E1=120000, E2=30000, D=256, D_OUT=64
// ---------------------------------------------------------------------------

#define N1C 50000
#define N2C 12000
#define N3C 3000
#define DF  256

// Scratch (static device allocations — no cudaMalloc allowed)
__device__ float g_agg0[N1C * DF];
__device__ float g_deg0[N1C];
__device__ float g_h1  [N1C * DF];
__device__ float g_agg1[N2C * DF];
__device__ float g_deg1[N2C];
__device__ float g_h2  [N2C * DF];
__device__ float g_agg2[N3C * DF];
__device__ float g_deg2[N3C];

// ---------------------------------------------------------------------------
// Edge aggregation: one warp per edge. Each lane moves 2 float4 (256 floats /
// warp) from h[src] and reduces them into agg[dst] with vector red (v4.f32).
// ---------------------------------------------------------------------------
__global__ void sage_aggregate(const float* __restrict__ h,
                               const int*   __restrict__ src,
                               const int*   __restrict__ dst,
                               float*       __restrict__ agg,
                               float*       __restrict__ deg,
                               int E)
{
    int w    = (int)((blockIdx.x * blockDim.x + threadIdx.x) >> 5);
    int lane = threadIdx.x & 31;
    if (w >= E) return;
    int s = src[w];
    int d = dst[w];
    const float4* hs = (const float4*)(h + (size_t)s * DF);
    float* ag = agg + (size_t)d * DF;
#pragma unroll
    for (int it = 0; it < 2; it++) {
        int j = lane + it * 32;
        float4 v = __ldg(hs + j);
        float* p = ag + j * 4;
        asm volatile("red.global.add.v4.f32 [%0], {%1, %2, %3, %4};"
                     :: "l"(p), "f"(v.x), "f"(v.y), "f"(v.z), "f"(v.w)
                     : "memory");
    }
    if (lane == 0) atomicAdd(deg + d, 1.0f);
}

// ---------------------------------------------------------------------------
// Fused dual-GEMM: out[i,:] = self[i,:] @ Ws + (agg[i,:]/max(deg[i],1)) @ Wn + b
// Implemented as a single K=512 GEMM ([self | scaled-agg] @ [Ws ; Wn]).
// Block tile 64x64, BK=16, 256 threads, 4x4 register micro-tile per thread.
// ---------------------------------------------------------------------------
template<int NCOLS>
__global__ __launch_bounds__(256)
void sage_gemm(const float* __restrict__ self,
               const float* __restrict__ agg,
               const float* __restrict__ deg,
               const float* __restrict__ Ws,
               const float* __restrict__ Wn,
               const float* __restrict__ bias,
               float*       __restrict__ out,
               int M, int relu)
{
    constexpr int BM = 64, BN = 64, BK = 16;
    __shared__ float As[BK][BM];   // A stored transposed: As[k][m]
    __shared__ float Bs[BK][BN];
    __shared__ float invd[BM];

    int tid = threadIdx.x;
    int bm0 = blockIdx.y * BM;
    int bn0 = blockIdx.x * BN;

    if (tid < BM) {
        int r = bm0 + tid;
        float dg = (r < M) ? deg[r] : 1.0f;
        invd[tid] = 1.0f / fmaxf(dg, 1.0f);
    }

    int tx = tid & 15;           // micro-tile column group
    int ty = tid >> 4;           // micro-tile row group

    // A-load indices: 256 threads cover 64x16 tile, float4 along K
    int rowA = tid >> 2;         // 0..63
    int cA   = (tid & 3) * 4;    // 0,4,8,12
    int rA   = bm0 + rowA;
    // B-load indices: 256 threads cover 16x64 tile, float4 along N
    int rowB = tid >> 4;         // 0..15
    int colB = (tid & 15) * 4;   // 0..60

    float acc[4][4] = {};

#pragma unroll 1
    for (int kt = 0; kt < 32; kt++) {
        bool second = (kt >= 16);
        int khalf = (kt & 15) * BK;          // 0..240 within the 256-wide half

        // stage global -> regs
        float4 v = make_float4(0.f, 0.f, 0.f, 0.f);
        if (rA < M) {
            const float* Aptr = second ? agg : self;
            v = *(const float4*)(Aptr + (size_t)rA * DF + khalf + cA);
            if (second) {
                float sc = invd[rowA];
                v.x *= sc; v.y *= sc; v.z *= sc; v.w *= sc;
            }
        }
        const float* W = second ? Wn : Ws;
        float4 wv = *(const float4*)(W + (size_t)(khalf + rowB) * NCOLS + bn0 + colB);

        __syncthreads();  // previous iteration's smem reads done
        As[cA + 0][rowA] = v.x;
        As[cA + 1][rowA] = v.y;
        As[cA + 2][rowA] = v.z;
        As[cA + 3][rowA] = v.w;
        *(float4*)&Bs[rowB][colB] = wv;
        __syncthreads();

#pragma unroll
        for (int kk = 0; kk < BK; kk++) {
            float4 a = *(const float4*)&As[kk][ty * 4];
            float4 b = *(const float4*)&Bs[kk][tx * 4];
            acc[0][0] += a.x * b.x; acc[0][1] += a.x * b.y;
            acc[0][2] += a.x * b.z; acc[0][3] += a.x * b.w;
            acc[1][0] += a.y * b.x; acc[1][1] += a.y * b.y;
            acc[1][2] += a.y * b.z; acc[1][3] += a.y * b.w;
            acc[2][0] += a.z * b.x; acc[2][1] += a.z * b.y;
            acc[2][2] += a.z * b.z; acc[2][3] += a.z * b.w;
            acc[3][0] += a.w * b.x; acc[3][1] += a.w * b.y;
            acc[3][2] += a.w * b.z; acc[3][3] += a.w * b.w;
        }
    }

    // epilogue: bias (+ relu), vectorized float4 stores
    float4 bv = *(const float4*)(bias + bn0 + tx * 4);
    int rbase = bm0 + ty * 4;
#pragma unroll
    for (int i = 0; i < 4; i++) {
        int r = rbase + i;
        if (r < M) {
            float4 o;
            o.x = acc[i][0] + bv.x;
            o.y = acc[i][1] + bv.y;
            o.z = acc[i][2] + bv.z;
            o.w = acc[i][3] + bv.w;
            if (relu) {
                o.x = fmaxf(o.x, 0.f); o.y = fmaxf(o.y, 0.f);
                o.z = fmaxf(o.z, 0.f); o.w = fmaxf(o.w, 0.f);
            }
            *(float4*)(out + (size_t)r * NCOLS + bn0 + tx * 4) = o;
        }
    }
}

// ---------------------------------------------------------------------------
// Launch: 3 x (memset agg/deg -> aggregate -> fused dual-GEMM)
// ---------------------------------------------------------------------------
extern "C" void kernel_launch(void* const* d_in, const int* in_sizes, int n_in,
                              void* d_out, int out_size)
{
    const float* x    = (const float*)d_in[0];
    const int*   src0 = (const int*)d_in[1];
    const int*   dst0 = (const int*)d_in[2];
    const int*   src1 = (const int*)d_in[3];
    const int*   dst1 = (const int*)d_in[4];
    const int*   src2 = (const int*)d_in[5];
    const int*   dst2 = (const int*)d_in[6];

    // Weights are always the last 9 inputs (robust to scalar num_dst* slots)
    int wb = n_in - 9;
    const float* Ws0 = (const float*)d_in[wb + 0];
    const float* Wn0 = (const float*)d_in[wb + 1];
    const float* b0  = (const float*)d_in[wb + 2];
    const float* Ws1 = (const float*)d_in[wb + 3];
    const float* Wn1 = (const float*)d_in[wb + 4];
    const float* b1  = (const float*)d_in[wb + 5];
    const float* Ws2 = (const float*)d_in[wb + 6];
    const float* Wn2 = (const float*)d_in[wb + 7];
    const float* b2  = (const float*)d_in[wb + 8];

    int E0 = in_sizes[1];
    int E1 = in_sizes[3];
    int E2 = in_sizes[5];

    float *agg0, *deg0, *h1, *agg1, *deg1, *h2, *agg2, *deg2;
    cudaGetSymbolAddress((void**)&agg0, g_agg0);
    cudaGetSymbolAddress((void**)&deg0, g_deg0);
    cudaGetSymbolAddress((void**)&h1,   g_h1);
    cudaGetSymbolAddress((void**)&agg1, g_agg1);
    cudaGetSymbolAddress((void**)&deg1, g_deg1);
    cudaGetSymbolAddress((void**)&h2,   g_h2);
    cudaGetSymbolAddress((void**)&agg2, g_agg2);
    cudaGetSymbolAddress((void**)&deg2, g_deg2);

    // ---- Layer 0: x -> h1 (N1 x 256) ----
    cudaMemsetAsync(agg0, 0, sizeof(float) * (size_t)N1C * DF);
    cudaMemsetAsync(deg0, 0, sizeof(float) * N1C);
    sage_aggregate<<<(E0 + 7) / 8, 256>>>(x, src0, dst0, agg0, deg0, E0);
    sage_gemm<256><<<dim3(4, (N1C + 63) / 64), 256>>>(
        x, agg0, deg0, Ws0, Wn0, b0, h1, N1C, 0);

    // ---- Layer 1: h1 -> h2 (N2 x 256), relu ----
    cudaMemsetAsync(agg1, 0, sizeof(float) * (size_t)N2C * DF);
    cudaMemsetAsync(deg1, 0, sizeof(float) * N2C);
    sage_aggregate<<<(E1 + 7) / 8, 256>>>(h1, src1, dst1, agg1, deg1, E1);
    sage_gemm<256><<<dim3(4, (N2C + 63) / 64), 256>>>(
        h1, agg1, deg1, Ws1, Wn1, b1, h2, N2C, 1);

    // ---- Layer 2: h2 -> out (N3 x 64) ----
    cudaMemsetAsync(agg2, 0, sizeof(float) * (size_t)N3C * DF);
    cudaMemsetAsync(deg2, 0, sizeof(float) * N3C);
    sage_aggregate<<<(E2 + 7) / 8, 256>>>(h2, src2, dst2, agg2, deg2, E2);
    sage_gemm<64><<<dim3(1, (N3C + 63) / 64), 256>>>(
        h2, agg2, deg2, Ws2, Wn2, b2, (float*)d_out, N3C, 0);
}

// round 3
// speedup vs baseline: 1.6866x; 1.6866x over previous
#include <cuda_runtime.h>
#include <cuda_bf16.h>
#include <cstdint>

// ---------------------------------------------------------------------------
// SAGE_37203006718147: 3-layer GraphSAGE on sm_103a.
// GEMM via mma.sync bf16 (split hi/lo, 3 terms) — tcgen05 is unavailable
// because the harness compiles PTX at virtual arch compute_103 (no 'a').
// ---------------------------------------------------------------------------

#define N1C 50000
#define N2C 12000
#define N3C 3000
#define DF  256

// ---- scratch (static device allocations; cudaMalloc forbidden) ----
__device__ float g_agg0[N1C * DF];
__device__ float g_deg0[N1C];
__device__ float g_h1  [N1C * DF];
__device__ float g_agg1[N2C * DF];
__device__ float g_deg1[N2C];
__device__ float g_h2  [N2C * DF];
__device__ float g_agg2[N3C * DF];
__device__ float g_deg2[N3C];
// transposed + bf16-split weights: [N][K=512], K-major
__device__ __nv_bfloat16 g_wt0h[256 * 512];
__device__ __nv_bfloat16 g_wt0l[256 * 512];
__device__ __nv_bfloat16 g_wt1h[256 * 512];
__device__ __nv_bfloat16 g_wt1l[256 * 512];
__device__ __nv_bfloat16 g_wt2h[64 * 512];
__device__ __nv_bfloat16 g_wt2l[64 * 512];

// ---------------------------------------------------------------------------
// helpers
// ---------------------------------------------------------------------------
__device__ __forceinline__ uint32_t smem_u32(const void* p) {
    uint32_t a;
    asm("{ .reg .u64 t; cvta.to.shared.u64 t, %1; cvt.u32.u64 %0, t; }"
        : "=r"(a) : "l"(p));
    return a;
}

__device__ __forceinline__ void ldsm4(uint32_t* r, uint32_t addr) {
    asm volatile("ldmatrix.sync.aligned.m8n8.x4.shared.b16 {%0,%1,%2,%3}, [%4];"
                 : "=r"(r[0]), "=r"(r[1]), "=r"(r[2]), "=r"(r[3]) : "r"(addr));
}

__device__ __forceinline__ void mma16816(float* c, const uint32_t* a,
                                         const uint32_t* b) {
    asm volatile(
        "mma.sync.aligned.m16n8k16.row.col.f32.bf16.bf16.f32 "
        "{%0,%1,%2,%3}, {%4,%5,%6,%7}, {%8,%9}, {%0,%1,%2,%3};"
        : "+f"(c[0]), "+f"(c[1]), "+f"(c[2]), "+f"(c[3])
        : "r"(a[0]), "r"(a[1]), "r"(a[2]), "r"(a[3]), "r"(b[0]), "r"(b[1]));
}

// split 8 fp32 -> 8 bf16 hi + 8 bf16 lo (packed as uint4 each)
__device__ __forceinline__ void split8(float4 a, float4 b, uint4& hi, uint4& lo) {
    float f[8] = {a.x, a.y, a.z, a.w, b.x, b.y, b.z, b.w};
    uint32_t H[8], L[8];
#pragma unroll
    for (int i = 0; i < 8; i++) {
        __nv_bfloat16 h = __float2bfloat16(f[i]);
        float r = f[i] - __bfloat162float(h);
        __nv_bfloat16 l = __float2bfloat16(r);
        H[i] = (uint32_t)__bfloat16_as_ushort(h);
        L[i] = (uint32_t)__bfloat16_as_ushort(l);
    }
    hi.x = H[0] | (H[1] << 16); hi.y = H[2] | (H[3] << 16);
    hi.z = H[4] | (H[5] << 16); hi.w = H[6] | (H[7] << 16);
    lo.x = L[0] | (L[1] << 16); lo.y = L[2] | (L[3] << 16);
    lo.z = L[4] | (L[5] << 16); lo.w = L[6] | (L[7] << 16);
}

// ---------------------------------------------------------------------------
// Weight prep: Wt[n][k] = (k<256 ? Ws[k][n] : Wn[k-256][n]), split bf16 hi/lo
// ---------------------------------------------------------------------------
__global__ void convert_weights(const float* __restrict__ Ws,
                                const float* __restrict__ Wn,
                                __nv_bfloat16* __restrict__ hi,
                                __nv_bfloat16* __restrict__ lo, int NC)
{
    int idx = blockIdx.x * blockDim.x + threadIdx.x;
    if (idx >= NC * 512) return;
    int n = idx >> 9, k = idx & 511;
    float v = (k < 256) ? Ws[(size_t)k * NC + n] : Wn[(size_t)(k - 256) * NC + n];
    __nv_bfloat16 h = __float2bfloat16(v);
    hi[idx] = h;
    lo[idx] = __float2bfloat16(v - __bfloat162float(h));
}

// ---------------------------------------------------------------------------
// Edge aggregation: one warp per edge; vector red.global.add.v4.f32
// ---------------------------------------------------------------------------
__global__ void sage_aggregate(const float* __restrict__ h,
                               const int*   __restrict__ src,
                               const int*   __restrict__ dst,
                               float*       __restrict__ agg,
                               float*       __restrict__ deg,
                               int E)
{
    int w    = (int)((blockIdx.x * blockDim.x + threadIdx.x) >> 5);
    int lane = threadIdx.x & 31;
    if (w >= E) return;
    int s = src[w];
    int d = dst[w];
    const float4* hs = (const float4*)(h + (size_t)s * DF);
    float* ag = agg + (size_t)d * DF;
#pragma unroll
    for (int it = 0; it < 2; it++) {
        int j = lane + it * 32;
        float4 v = __ldg(hs + j);
        float* p = ag + j * 4;
        asm volatile("red.global.add.v4.f32 [%0], {%1, %2, %3, %4};"
                     :: "l"(p), "f"(v.x), "f"(v.y), "f"(v.z), "f"(v.w)
                     : "memory");
    }
    if (lane == 0) atomicAdd(deg + d, 1.0f);
}

// ---------------------------------------------------------------------------
// mma.sync dual-GEMM:
//   out[m, bn0:bn0+BN] = [self | agg/deg](m, 0:512) @ Wt^T (+bias, relu?)
// CTA tile 128xBN, BK=32, 8 warps (4x2), warp tile 32x(BN/2).
// A: gmem fp32 -> regs -> bf16 hi/lo smem. B: cp.async bf16 hi/lo smem.
// Double-buffered, one sync per K-iter, 3 split-term HMMA.
// ---------------------------------------------------------------------------
template<int BN>
__global__ __launch_bounds__(256)
void sage_gemm_mma(const float* __restrict__ self,
                   const float* __restrict__ agg,
                   const float* __restrict__ deg,
                   const __nv_bfloat16* __restrict__ wth,
                   const __nv_bfloat16* __restrict__ wtl,
                   const float* __restrict__ bias,
                   float*       __restrict__ out,
                   int M, int NCOLS, int relu)
{
    constexpr int APITCH = 80;            // bytes per smem row (64B data + 16 pad)
    constexpr int ASTG   = 128 * APITCH;  // 10240 B per A matrix
    constexpr int BSTG   = BN * APITCH;   // per B matrix
    constexpr int SS     = 2 * ASTG + 2 * BSTG;  // stage: Ah,Al,Bh,Bl
    constexpr int NT8    = BN / 16;       // n8-tiles per warp (warp covers BN/2)
    constexpr int NBSEG  = (BN * 4) / 256;  // cp.async 16B segs/thread/matrix
    constexpr int WN     = BN / 2;

    extern __shared__ char smem[];
    float* s_invd = (float*)smem;
    char*  stg    = smem + 1024;
    uint32_t stg_u = smem_u32(stg);

    int tid  = threadIdx.x;
    int lane = tid & 31, wid = tid >> 5;
    int wm = wid & 3, wn = wid >> 2;
    int bm0 = blockIdx.y * 128, bn0 = blockIdx.x * BN;

    if (tid < 128) {
        int r = bm0 + tid;
        float dg = (r < M) ? deg[r] : 1.0f;
        s_invd[tid] = 1.0f / fmaxf(dg, 1.0f);
    }
    __syncthreads();

    // ---- staging lambdas ----
    uint4 ah[2], al[2];

    auto prepA = [&](int kt) {
        int kg = kt * 32;
        const float* Asrc = (kg < 256) ? self : agg;
        int kc = kg & 255;
        bool isAgg = (kg >= 256);
#pragma unroll
        for (int i = 0; i < 2; i++) {
            int seg = tid + 256 * i;          // 0..511
            int row = seg >> 2, c8 = (seg & 3) * 8;
            int gr = bm0 + row;
            float4 v0 = make_float4(0.f, 0.f, 0.f, 0.f), v1 = v0;
            if (gr < M) {
                const float4* p = (const float4*)(Asrc + (size_t)gr * DF + kc + c8);
                v0 = __ldg(p); v1 = __ldg(p + 1);
                if (isAgg) {
                    float sc = s_invd[row];
                    v0.x *= sc; v0.y *= sc; v0.z *= sc; v0.w *= sc;
                    v1.x *= sc; v1.y *= sc; v1.z *= sc; v1.w *= sc;
                }
            }
            split8(v0, v1, ah[i], al[i]);
        }
    };

    auto storeA = [&](int s) {
        char* base = stg + s * SS;
#pragma unroll
        for (int i = 0; i < 2; i++) {
            int seg = tid + 256 * i;
            int row = seg >> 2, cc = (seg & 3) * 16;
            *(uint4*)(base + row * APITCH + cc)        = ah[i];
            *(uint4*)(base + ASTG + row * APITCH + cc) = al[i];
        }
    };

    auto issueB = [&](int kt, int s) {
        int kg = kt * 32;
        uint32_t bbase = stg_u + s * SS + 2 * ASTG;
#pragma unroll
        for (int i = 0; i < NBSEG; i++) {
            int seg = tid + 256 * i;
            int row = seg >> 2, cc = (seg & 3) * 16;
            uint32_t sa = bbase + row * APITCH + cc;
            const __nv_bfloat16* g = wth + (size_t)(bn0 + row) * 512 + kg + (seg & 3) * 8;
            asm volatile("cp.async.cg.shared.global [%0], [%1], 16;"
                         :: "r"(sa), "l"(g));
        }
#pragma unroll
        for (int i = 0; i < NBSEG; i++) {
            int seg = tid + 256 * i;
            int row = seg >> 2, cc = (seg & 3) * 16;
            uint32_t sa = bbase + BSTG + row * APITCH + cc;
            const __nv_bfloat16* g = wtl + (size_t)(bn0 + row) * 512 + kg + (seg & 3) * 8;
            asm volatile("cp.async.cg.shared.global [%0], [%1], 16;"
                         :: "r"(sa), "l"(g));
        }
        asm volatile("cp.async.commit_group;" ::: "memory");
    };

    float acc[2][NT8][4] = {};

    issueB(0, 0);
    prepA(0);

#pragma unroll 1
    for (int kt = 0; kt < 16; kt++) {
        int s = kt & 1;
        storeA(s);
        asm volatile("cp.async.wait_group 0;" ::: "memory");
        __syncthreads();
        if (kt < 15) {
            issueB(kt + 1, 1 - s);
            prepA(kt + 1);
        }

        uint32_t abase = stg_u + s * SS;
        uint32_t bbase = abase + 2 * ASTG;
#pragma unroll
        for (int ks = 0; ks < 2; ks++) {
            uint32_t afh[2][4], afl[2][4], bfh[NT8][2], bfl[NT8][2];
            // A fragments: tiles (rows 0-7,k0),(rows 8-15,k0),(0-7,k+8),(8-15,k+8)
#pragma unroll
            for (int mt = 0; mt < 2; mt++) {
                int r  = wm * 32 + mt * 16 + (lane & 7) + ((lane >> 3) & 1) * 8;
                int kb = ks * 16 + ((lane >> 4) & 1) * 8;
                uint32_t ad = abase + r * APITCH + kb * 2;
                ldsm4(afh[mt], ad);
                ldsm4(afl[mt], ad + ASTG);
            }
            // B fragments: tiles (n0-7,k0),(n0-7,k+8),(n8-15,k0),(n8-15,k+8)
#pragma unroll
            for (int p = 0; p < NT8 / 2; p++) {
                int n  = wn * WN + p * 16 + (lane & 7) + ((lane >> 4) & 1) * 8;
                int kb = ks * 16 + ((lane >> 3) & 1) * 8;
                uint32_t bd = bbase + n * APITCH + kb * 2;
                uint32_t th[4], tl[4];
                ldsm4(th, bd);
                ldsm4(tl, bd + BSTG);
                bfh[2 * p][0] = th[0]; bfh[2 * p][1] = th[1];
                bfh[2 * p + 1][0] = th[2]; bfh[2 * p + 1][1] = th[3];
                bfl[2 * p][0] = tl[0]; bfl[2 * p][1] = tl[1];
                bfl[2 * p + 1][0] = tl[2]; bfl[2 * p + 1][1] = tl[3];
            }
#pragma unroll
            for (int mt = 0; mt < 2; mt++)
#pragma unroll
                for (int nt = 0; nt < NT8; nt++) {
                    mma16816(acc[mt][nt], afh[mt], bfh[nt]);
                    mma16816(acc[mt][nt], afh[mt], bfl[nt]);
                    mma16816(acc[mt][nt], afl[mt], bfh[nt]);
                }
        }
    }

    // ---- epilogue: bias (+relu), float2 stores ----
#pragma unroll
    for (int mt = 0; mt < 2; mt++) {
        int r0 = bm0 + wm * 32 + mt * 16 + (lane >> 2);
#pragma unroll
        for (int nt = 0; nt < NT8; nt++) {
            int col = bn0 + wn * WN + nt * 8 + (lane & 3) * 2;
            float2 bv = *(const float2*)(bias + col);
            float2 o0, o1;
            o0.x = acc[mt][nt][0] + bv.x; o0.y = acc[mt][nt][1] + bv.y;
            o1.x = acc[mt][nt][2] + bv.x; o1.y = acc[mt][nt][3] + bv.y;
            if (relu) {
                o0.x = fmaxf(o0.x, 0.f); o0.y = fmaxf(o0.y, 0.f);
                o1.x = fmaxf(o1.x, 0.f); o1.y = fmaxf(o1.y, 0.f);
            }
            if (r0 < M)
                *(float2*)(out + (size_t)r0 * NCOLS + col) = o0;
            if (r0 + 8 < M)
                *(float2*)(out + (size_t)(r0 + 8) * NCOLS + col) = o1;
        }
    }
}

// ---------------------------------------------------------------------------
// Launch
// ---------------------------------------------------------------------------
extern "C" void kernel_launch(void* const* d_in, const int* in_sizes, int n_in,
                              void* d_out, int out_size)
{
    const float* x    = (const float*)d_in[0];
    const int*   src0 = (const int*)d_in[1];
    const int*   dst0 = (const int*)d_in[2];
    const int*   src1 = (const int*)d_in[3];
    const int*   dst1 = (const int*)d_in[4];
    const int*   src2 = (const int*)d_in[5];
    const int*   dst2 = (const int*)d_in[6];

    int wb = n_in - 9;
    const float* Ws0 = (const float*)d_in[wb + 0];
    const float* Wn0 = (const float*)d_in[wb + 1];
    const float* b0  = (const float*)d_in[wb + 2];
    const float* Ws1 = (const float*)d_in[wb + 3];
    const float* Wn1 = (const float*)d_in[wb + 4];
    const float* b1  = (const float*)d_in[wb + 5];
    const float* Ws2 = (const float*)d_in[wb + 6];
    const float* Wn2 = (const float*)d_in[wb + 7];
    const float* b2  = (const float*)d_in[wb + 8];

    int E0 = in_sizes[1];
    int E1 = in_sizes[3];
    int E2 = in_sizes[5];

    float *agg0, *deg0, *h1, *agg1, *deg1, *h2, *agg2, *deg2;
    __nv_bfloat16 *wt0h, *wt0l, *wt1h, *wt1l, *wt2h, *wt2l;
    cudaGetSymbolAddress((void**)&agg0, g_agg0);
    cudaGetSymbolAddress((void**)&deg0, g_deg0);
    cudaGetSymbolAddress((void**)&h1,   g_h1);
    cudaGetSymbolAddress((void**)&agg1, g_agg1);
    cudaGetSymbolAddress((void**)&deg1, g_deg1);
    cudaGetSymbolAddress((void**)&h2,   g_h2);
    cudaGetSymbolAddress((void**)&agg2, g_agg2);
    cudaGetSymbolAddress((void**)&deg2, g_deg2);
    cudaGetSymbolAddress((void**)&wt0h, g_wt0h);
    cudaGetSymbolAddress((void**)&wt0l, g_wt0l);
    cudaGetSymbolAddress((void**)&wt1h, g_wt1h);
    cudaGetSymbolAddress((void**)&wt1l, g_wt1l);
    cudaGetSymbolAddress((void**)&wt2h, g_wt2h);
    cudaGetSymbolAddress((void**)&wt2l, g_wt2l);

    // dynamic smem: 1024 (invd+pad) + 2 stages
    const int SMEM128 = 1024 + 2 * (2 * 128 * 80 + 2 * 128 * 80);  // 82944
    const int SMEM64  = 1024 + 2 * (2 * 128 * 80 + 2 * 64 * 80);   // 62464
    cudaFuncSetAttribute(sage_gemm_mma<128>,
                         cudaFuncAttributeMaxDynamicSharedMemorySize, SMEM128);
    cudaFuncSetAttribute(sage_gemm_mma<64>,
                         cudaFuncAttributeMaxDynamicSharedMemorySize, SMEM64);

    // weight prep
    convert_weights<<<(256 * 512 + 255) / 256, 256>>>(Ws0, Wn0, wt0h, wt0l, 256);
    convert_weights<<<(256 * 512 + 255) / 256, 256>>>(Ws1, Wn1, wt1h, wt1l, 256);
    convert_weights<<<(64  * 512 + 255) / 256, 256>>>(Ws2, Wn2, wt2h, wt2l, 64);

    // ---- Layer 0: x -> h1 (N1 x 256) ----
    cudaMemsetAsync(agg0, 0, sizeof(float) * (size_t)N1C * DF);
    cudaMemsetAsync(deg0, 0, sizeof(float) * N1C);
    sage_aggregate<<<(E0 + 7) / 8, 256>>>(x, src0, dst0, agg0, deg0, E0);
    sage_gemm_mma<128><<<dim3(2, (N1C + 127) / 128), 256, SMEM128>>>(
        x, agg0, deg0, wt0h, wt0l, b0, h1, N1C, 256, 0);

    // ---- Layer 1: h1 -> h2 (N2 x 256), relu ----
    cudaMemsetAsync(agg1, 0, sizeof(float) * (size_t)N2C * DF);
    cudaMemsetAsync(deg1, 0, sizeof(float) * N2C);
    sage_aggregate<<<(E1 + 7) / 8, 256>>>(h1, src1, dst1, agg1, deg1, E1);
    sage_gemm_mma<128><<<dim3(2, (N2C + 127) / 128), 256, SMEM128>>>(
        h1, agg1, deg1, wt1h, wt1l, b1, h2, N2C, 256, 1);

    // ---- Layer 2: h2 -> out (N3 x 64) ----
    cudaMemsetAsync(agg2, 0, sizeof(float) * (size_t)N3C * DF);
    cudaMemsetAsync(deg2, 0, sizeof(float) * N3C);
    sage_aggregate<<<(E2 + 7) / 8, 256>>>(h2, src2, dst2, agg2, deg2, E2);
    sage_gemm_mma<64><<<dim3(1, (N3C + 127) / 128), 256, SMEM64>>>(
        h2, agg2, deg2, wt2h, wt2l, b2, (float*)d_out, N3C, 64, 0);
}

// round 4
// speedup vs baseline: 1.8191x; 1.0786x over previous
#include <cuda_runtime.h>
#include <cuda_fp16.h>
#include <cstdint>

// ---------------------------------------------------------------------------
// SAGE_37203006718147: 3-layer GraphSAGE on sm_103a.
// GEMM via mma.sync fp16 2-term split (C = Ah*Bh + Al*Bh), tensor-core HMMA.
// tcgen05 unavailable: harness compiles at virtual arch compute_103 (no 'a').
// ---------------------------------------------------------------------------

#define N1C 50000
#define N2C 12000
#define N3C 3000
#define DF  256

// ---- scratch (static device allocations; cudaMalloc forbidden) ----
__device__ float g_agg0[N1C * DF];
__device__ float g_deg0[N1C];
__device__ float g_h1  [N1C * DF];
__device__ float g_agg1[N2C * DF];
__device__ float g_deg1[N2C];
__device__ float g_h2  [N2C * DF];
__device__ float g_agg2[N3C * DF];
__device__ float g_deg2[N3C];
// transposed fp16 weights: [N][K=512], K-major
__device__ __half g_wt0[256 * 512];
__device__ __half g_wt1[256 * 512];
__device__ __half g_wt2[64 * 512];

// ---------------------------------------------------------------------------
// helpers
// ---------------------------------------------------------------------------
__device__ __forceinline__ uint32_t smem_u32(const void* p) {
    uint32_t a;
    asm("{ .reg .u64 t; cvta.to.shared.u64 t, %1; cvt.u32.u64 %0, t; }"
        : "=r"(a) : "l"(p));
    return a;
}

__device__ __forceinline__ void ldsm4(uint32_t* r, uint32_t addr) {
    asm volatile("ldmatrix.sync.aligned.m8n8.x4.shared.b16 {%0,%1,%2,%3}, [%4];"
                 : "=r"(r[0]), "=r"(r[1]), "=r"(r[2]), "=r"(r[3]) : "r"(addr));
}

__device__ __forceinline__ void mma16816(float* c, const uint32_t* a,
                                         const uint32_t* b) {
    asm volatile(
        "mma.sync.aligned.m16n8k16.row.col.f32.f16.f16.f32 "
        "{%0,%1,%2,%3}, {%4,%5,%6,%7}, {%8,%9}, {%0,%1,%2,%3};"
        : "+f"(c[0]), "+f"(c[1]), "+f"(c[2]), "+f"(c[3])
        : "r"(a[0]), "r"(a[1]), "r"(a[2]), "r"(a[3]), "r"(b[0]), "r"(b[1]));
}

// split 8 fp32 -> 8 fp16 hi + 8 fp16 lo (packed as uint4 each)
__device__ __forceinline__ void split8(float4 a, float4 b, uint4& hi, uint4& lo) {
    float f[8] = {a.x, a.y, a.z, a.w, b.x, b.y, b.z, b.w};
    uint32_t H[8], L[8];
#pragma unroll
    for (int i = 0; i < 8; i++) {
        __half h = __float2half_rn(f[i]);
        float r = f[i] - __half2float(h);
        __half l = __float2half_rn(r);
        H[i] = (uint32_t)__half_as_ushort(h);
        L[i] = (uint32_t)__half_as_ushort(l);
    }
    hi.x = H[0] | (H[1] << 16); hi.y = H[2] | (H[3] << 16);
    hi.z = H[4] | (H[5] << 16); hi.w = H[6] | (H[7] << 16);
    lo.x = L[0] | (L[1] << 16); lo.y = L[2] | (L[3] << 16);
    lo.z = L[4] | (L[5] << 16); lo.w = L[6] | (L[7] << 16);
}

// ---------------------------------------------------------------------------
// Weight prep: Wt[n][k] = fp16(k<256 ? Ws[k][n] : Wn[k-256][n]), K-major
// ---------------------------------------------------------------------------
__global__ void convert_weights(const float* __restrict__ Ws,
                                const float* __restrict__ Wn,
                                __half* __restrict__ wt, int NC)
{
    int idx = blockIdx.x * blockDim.x + threadIdx.x;
    if (idx >= NC * 512) return;
    int n = idx >> 9, k = idx & 511;
    float v = (k < 256) ? Ws[(size_t)k * NC + n] : Wn[(size_t)(k - 256) * NC + n];
    wt[idx] = __float2half_rn(v);
}

// ---------------------------------------------------------------------------
// Edge aggregation: 4 edges per warp, batched LDG.128 (MLP=8) then vector REDs
// ---------------------------------------------------------------------------
__global__ void sage_aggregate(const float* __restrict__ h,
                               const int*   __restrict__ src,
                               const int*   __restrict__ dst,
                               float*       __restrict__ agg,
                               float*       __restrict__ deg,
                               int E)
{
    int warp = (int)(blockIdx.x * (blockDim.x >> 5) + (threadIdx.x >> 5));
    int lane = threadIdx.x & 31;
    int e0 = warp * 4;
    if (e0 >= E) return;
    int n = E - e0;
    if (n > 4) n = 4;

    int s[4], d[4];
#pragma unroll
    for (int e = 0; e < 4; e++) {
        int idx = (e < n) ? e0 + e : e0;
        s[e] = __ldg(src + idx);
        d[e] = __ldg(dst + idx);
    }

    float4 v[4][2];
#pragma unroll
    for (int e = 0; e < 4; e++) {
        if (e < n) {
            const float4* hs = (const float4*)(h + (size_t)s[e] * DF) + lane;
            v[e][0] = __ldg(hs);
            v[e][1] = __ldg(hs + 32);
        }
    }

#pragma unroll
    for (int e = 0; e < 4; e++) {
        if (e < n) {
            float* p = agg + (size_t)d[e] * DF + lane * 4;
            asm volatile("red.global.add.v4.f32 [%0], {%1, %2, %3, %4};"
                         :: "l"(p), "f"(v[e][0].x), "f"(v[e][0].y),
                            "f"(v[e][0].z), "f"(v[e][0].w) : "memory");
            asm volatile("red.global.add.v4.f32 [%0], {%1, %2, %3, %4};"
                         :: "l"(p + 128), "f"(v[e][1].x), "f"(v[e][1].y),
                            "f"(v[e][1].z), "f"(v[e][1].w) : "memory");
        }
    }
#pragma unroll
    for (int e = 0; e < 4; e++)
        if (lane == e && e < n) atomicAdd(deg + d[e], 1.0f);
}

// ---------------------------------------------------------------------------
// mma.sync dual-GEMM (fp16 2-term):
//   out[m, bn0:bn0+BN] = [self | agg/deg](m, 0:512) @ Wt^T (+bias, relu?)
// CTA tile 128xBN, BK=32, 8 warps (4x2), warp tile 32x(BN/2).
// A: gmem fp32 -> regs -> fp16 hi/lo smem. B: cp.async fp16 smem.
// Double-buffered, one sync per K-iter, 2 split-term HMMA.
// ---------------------------------------------------------------------------
template<int BN>
__global__ __launch_bounds__(256)
void sage_gemm_mma(const float* __restrict__ self,
                   const float* __restrict__ agg,
                   const float* __restrict__ deg,
                   const __half* __restrict__ wt,
                   const float* __restrict__ bias,
                   float*       __restrict__ out,
                   int M, int NCOLS, int relu)
{
    constexpr int APITCH = 80;            // bytes/smem row (64B data + 16 pad)
    constexpr int ASTG   = 128 * APITCH;  // 10240 B per A matrix
    constexpr int BSTG   = BN * APITCH;   // B matrix (hi only)
    constexpr int SS     = 2 * ASTG + BSTG;  // stage: Ah,Al,Bh
    constexpr int NT8    = BN / 16;       // n8-tiles per warp
    constexpr int NBSEG  = (BN * 4) / 256;  // cp.async 16B segs/thread
    constexpr int WN     = BN / 2;

    extern __shared__ char smem[];
    float* s_invd = (float*)smem;
    char*  stg    = smem + 1024;
    uint32_t stg_u = smem_u32(stg);

    int tid  = threadIdx.x;
    int lane = tid & 31, wid = tid >> 5;
    int wm = wid & 3, wn = wid >> 2;
    int bm0 = blockIdx.y * 128, bn0 = blockIdx.x * BN;

    if (tid < 128) {
        int r = bm0 + tid;
        float dg = (r < M) ? deg[r] : 1.0f;
        s_invd[tid] = 1.0f / fmaxf(dg, 1.0f);
    }
    __syncthreads();

    uint4 ah[2], al[2];

    auto prepA = [&](int kt) {
        int kg = kt * 32;
        const float* Asrc = (kg < 256) ? self : agg;
        int kc = kg & 255;
        bool isAgg = (kg >= 256);
#pragma unroll
        for (int i = 0; i < 2; i++) {
            int seg = tid + 256 * i;          // 0..511
            int row = seg >> 2, c8 = (seg & 3) * 8;
            int gr = bm0 + row;
            float4 v0 = make_float4(0.f, 0.f, 0.f, 0.f), v1 = v0;
            if (gr < M) {
                const float4* p = (const float4*)(Asrc + (size_t)gr * DF + kc + c8);
                v0 = __ldg(p); v1 = __ldg(p + 1);
                if (isAgg) {
                    float sc = s_invd[row];
                    v0.x *= sc; v0.y *= sc; v0.z *= sc; v0.w *= sc;
                    v1.x *= sc; v1.y *= sc; v1.z *= sc; v1.w *= sc;
                }
            }
            split8(v0, v1, ah[i], al[i]);
        }
    };

    auto storeA = [&](int s) {
        char* base = stg + s * SS;
#pragma unroll
        for (int i = 0; i < 2; i++) {
            int seg = tid + 256 * i;
            int row = seg >> 2, cc = (seg & 3) * 16;
            *(uint4*)(base + row * APITCH + cc)        = ah[i];
            *(uint4*)(base + ASTG + row * APITCH + cc) = al[i];
        }
    };

    auto issueB = [&](int kt, int s) {
        int kg = kt * 32;
        uint32_t bbase = stg_u + s * SS + 2 * ASTG;
#pragma unroll
        for (int i = 0; i < NBSEG; i++) {
            int seg = tid + 256 * i;
            int row = seg >> 2, cc = (seg & 3) * 16;
            uint32_t sa = bbase + row * APITCH + cc;
            const __half* g = wt + (size_t)(bn0 + row) * 512 + kg + (seg & 3) * 8;
            asm volatile("cp.async.cg.shared.global [%0], [%1], 16;"
                         :: "r"(sa), "l"(g));
        }
        asm volatile("cp.async.commit_group;" ::: "memory");
    };

    float acc[2][NT8][4] = {};

    issueB(0, 0);
    prepA(0);

#pragma unroll 1
    for (int kt = 0; kt < 16; kt++) {
        int s = kt & 1;
        storeA(s);
        asm volatile("cp.async.wait_group 0;" ::: "memory");
        __syncthreads();
        if (kt < 15) {
            issueB(kt + 1, 1 - s);
            prepA(kt + 1);
        }

        uint32_t abase = stg_u + s * SS;
        uint32_t bbase = abase + 2 * ASTG;
#pragma unroll
        for (int ks = 0; ks < 2; ks++) {
            uint32_t afh[2][4], afl[2][4], bf[NT8][2];
#pragma unroll
            for (int mt = 0; mt < 2; mt++) {
                int r  = wm * 32 + mt * 16 + (lane & 7) + ((lane >> 3) & 1) * 8;
                int kb = ks * 16 + ((lane >> 4) & 1) * 8;
                uint32_t ad = abase + r * APITCH + kb * 2;
                ldsm4(afh[mt], ad);
                ldsm4(afl[mt], ad + ASTG);
            }
#pragma unroll
            for (int p = 0; p < NT8 / 2; p++) {
                int n  = wn * WN + p * 16 + (lane & 7) + ((lane >> 4) & 1) * 8;
                int kb = ks * 16 + ((lane >> 3) & 1) * 8;
                uint32_t bd = bbase + n * APITCH + kb * 2;
                uint32_t th[4];
                ldsm4(th, bd);
                bf[2 * p][0] = th[0]; bf[2 * p][1] = th[1];
                bf[2 * p + 1][0] = th[2]; bf[2 * p + 1][1] = th[3];
            }
#pragma unroll
            for (int mt = 0; mt < 2; mt++)
#pragma unroll
                for (int nt = 0; nt < NT8; nt++) {
                    mma16816(acc[mt][nt], afh[mt], bf[nt]);
                    mma16816(acc[mt][nt], afl[mt], bf[nt]);
                }
        }
    }

    // ---- epilogue: bias (+relu), float2 stores ----
#pragma unroll
    for (int mt = 0; mt < 2; mt++) {
        int r0 = bm0 + wm * 32 + mt * 16 + (lane >> 2);
#pragma unroll
        for (int nt = 0; nt < NT8; nt++) {
            int col = bn0 + wn * WN + nt * 8 + (lane & 3) * 2;
            float2 bv = *(const float2*)(bias + col);
            float2 o0, o1;
            o0.x = acc[mt][nt][0] + bv.x; o0.y = acc[mt][nt][1] + bv.y;
            o1.x = acc[mt][nt][2] + bv.x; o1.y = acc[mt][nt][3] + bv.y;
            if (relu) {
                o0.x = fmaxf(o0.x, 0.f); o0.y = fmaxf(o0.y, 0.f);
                o1.x = fmaxf(o1.x, 0.f); o1.y = fmaxf(o1.y, 0.f);
            }
            if (r0 < M)
                *(float2*)(out + (size_t)r0 * NCOLS + col) = o0;
            if (r0 + 8 < M)
                *(float2*)(out + (size_t)(r0 + 8) * NCOLS + col) = o1;
        }
    }
}

// ---------------------------------------------------------------------------
// Launch
// ---------------------------------------------------------------------------
extern "C" void kernel_launch(void* const* d_in, const int* in_sizes, int n_in,
                              void* d_out, int out_size)
{
    const float* x    = (const float*)d_in[0];
    const int*   src0 = (const int*)d_in[1];
    const int*   dst0 = (const int*)d_in[2];
    const int*   src1 = (const int*)d_in[3];
    const int*   dst1 = (const int*)d_in[4];
    const int*   src2 = (const int*)d_in[5];
    const int*   dst2 = (const int*)d_in[6];

    int wb = n_in - 9;
    const float* Ws0 = (const float*)d_in[wb + 0];
    const float* Wn0 = (const float*)d_in[wb + 1];
    const float* b0  = (const float*)d_in[wb + 2];
    const float* Ws1 = (const float*)d_in[wb + 3];
    const float* Wn1 = (const float*)d_in[wb + 4];
    const float* b1  = (const float*)d_in[wb + 5];
    const float* Ws2 = (const float*)d_in[wb + 6];
    const float* Wn2 = (const float*)d_in[wb + 7];
    const float* b2  = (const float*)d_in[wb + 8];

    int E0 = in_sizes[1];
    int E1 = in_sizes[3];
    int E2 = in_sizes[5];

    float *agg0, *deg0, *h1, *agg1, *deg1, *h2, *agg2, *deg2;
    __half *wt0, *wt1, *wt2;
    cudaGetSymbolAddress((void**)&agg0, g_agg0);
    cudaGetSymbolAddress((void**)&deg0, g_deg0);
    cudaGetSymbolAddress((void**)&h1,   g_h1);
    cudaGetSymbolAddress((void**)&agg1, g_agg1);
    cudaGetSymbolAddress((void**)&deg1, g_deg1);
    cudaGetSymbolAddress((void**)&h2,   g_h2);
    cudaGetSymbolAddress((void**)&agg2, g_agg2);
    cudaGetSymbolAddress((void**)&deg2, g_deg2);
    cudaGetSymbolAddress((void**)&wt0,  g_wt0);
    cudaGetSymbolAddress((void**)&wt1,  g_wt1);
    cudaGetSymbolAddress((void**)&wt2,  g_wt2);

    // dynamic smem: 1024 (invd) + 2 stages (Ah, Al, Bh)
    const int SMEM128 = 1024 + 2 * (2 * 128 * 80 + 128 * 80);  // 62464
    const int SMEM64  = 1024 + 2 * (2 * 128 * 80 + 64 * 80);   // 52224
    cudaFuncSetAttribute(sage_gemm_mma<128>,
                         cudaFuncAttributeMaxDynamicSharedMemorySize, SMEM128);
    cudaFuncSetAttribute(sage_gemm_mma<64>,
                         cudaFuncAttributeMaxDynamicSharedMemorySize, SMEM64);

    // weight prep
    convert_weights<<<(256 * 512 + 255) / 256, 256>>>(Ws0, Wn0, wt0, 256);
    convert_weights<<<(256 * 512 + 255) / 256, 256>>>(Ws1, Wn1, wt1, 256);
    convert_weights<<<(64  * 512 + 255) / 256, 256>>>(Ws2, Wn2, wt2, 64);

    // ---- Layer 0: x -> h1 (N1 x 256) ----
    cudaMemsetAsync(agg0, 0, sizeof(float) * (size_t)N1C * DF);
    cudaMemsetAsync(deg0, 0, sizeof(float) * N1C);
    sage_aggregate<<<(E0 + 31) / 32, 256>>>(x, src0, dst0, agg0, deg0, E0);
    sage_gemm_mma<128><<<dim3(2, (N1C + 127) / 128), 256, SMEM128>>>(
        x, agg0, deg0, wt0, b0, h1, N1C, 256, 0);

    // ---- Layer 1: h1 -> h2 (N2 x 256), relu ----
    cudaMemsetAsync(agg1, 0, sizeof(float) * (size_t)N2C * DF);
    cudaMemsetAsync(deg1, 0, sizeof(float) * N2C);
    sage_aggregate<<<(E1 + 31) / 32, 256>>>(h1, src1, dst1, agg1, deg1, E1);
    sage_gemm_mma<128><<<dim3(2, (N2C + 127) / 128), 256, SMEM128>>>(
        h1, agg1, deg1, wt1, b1, h2, N2C, 256, 1);

    // ---- Layer 2: h2 -> out (N3 x 64) ----
    cudaMemsetAsync(agg2, 0, sizeof(float) * (size_t)N3C * DF);
    cudaMemsetAsync(deg2, 0, sizeof(float) * N3C);
    sage_aggregate<<<(E2 + 31) / 32, 256>>>(h2, src2, dst2, agg2, deg2, E2);
    sage_gemm_mma<64><<<dim3(1, (N3C + 127) / 128), 256, SMEM64>>>(
        h2, agg2, deg2, wt2, b2, (float*)d_out, N3C, 64, 0);
}